// round 7
// baseline (speedup 1.0000x reference)
#include <cuda_runtime.h>
#include <cstddef>

// One warp per row of 1024 floats, persistent grid-stride over rows,
// SOFTWARE-PIPELINED: next row's 8 float4 global loads are issued before
// computing the current row, so each warp keeps 512B of DRAM traffic in
// flight during its entire compute phase (fixes the latency-bound duty
// cycle seen in R5/R6: nothing saturated, DRAM stuck at ~70%).
//
// Thread owns 32 elements i = 128k + 4*lane + b, held as v[c], c = 4k+b.
// FWHT1024 = FWHT32 over c-bits (i bits 0,1,7,8,9)
//          ∘ FWHT32 over lane-bits (i bits 2..6) via conflict-free
//            stride-33 padded-SMEM 32x32 transpose. No shuffles.

#define NWARPS 8

__global__ void __launch_bounds__(256, 2)
fwht1024_kernel(const float* __restrict__ x,
                const float* __restrict__ scale,
                const float* __restrict__ shift,
                float* __restrict__ out,
                int nrows, int warp_stride)
{
    __shared__ float xch[NWARPS][32 * 33];   // 4224 B/warp, 33.8 KB/block
    const int wlocal = threadIdx.x >> 5;
    const int lane   = threadIdx.x & 31;
    float* __restrict__ sm = xch[wlocal];

    const float4* __restrict__ xin4 = reinterpret_cast<const float4*>(x);
    float4* __restrict__ xo4        = reinterpret_cast<float4*>(out);
    const float4* __restrict__ sc4  = reinterpret_cast<const float4*>(scale);
    const float4* __restrict__ sh4  = reinterpret_cast<const float4*>(shift);
    const float inv = 0.03125f;              // 1/sqrt(1024)

    int row = blockIdx.x * NWARPS + wlocal;

    // ---- prologue: load first row ----
    float4 t[8];
    if (row < nrows) {
        const float4* __restrict__ p = xin4 + (size_t)row * 256u;
        #pragma unroll
        for (int k = 0; k < 8; k++)
            t[k] = __ldcs(&p[k * 32 + lane]);
    }

    while (row < nrows) {
        const int next = row + warp_stride;

        // ---- prefetch next row FIRST: overlaps the whole compute below ----
        float4 tn[8];
        if (next < nrows) {
            const float4* __restrict__ p = xin4 + (size_t)next * 256u;
            #pragma unroll
            for (int k = 0; k < 8; k++)
                tn[k] = __ldcs(&p[k * 32 + lane]);
        }

        // ---- unpack current row ----
        float v[32];
        #pragma unroll
        for (int k = 0; k < 8; k++) {
            v[4*k+0] = t[k].x; v[4*k+1] = t[k].y;
            v[4*k+2] = t[k].z; v[4*k+3] = t[k].w;
        }

        // ---- FWHT32 over register index (element bits 0,1,7,8,9) ----
        #pragma unroll
        for (int m = 1; m < 32; m <<= 1) {
            #pragma unroll
            for (int p = 0; p < 32; p++) {
                if ((p & m) == 0) {
                    float u = v[p], w = v[p | m];
                    v[p]     = u + w;
                    v[p | m] = u - w;
                }
            }
        }

        // ---- transpose: write sm[lane*33+c] (bank lane+c: CF),
        //                 read  sm[j*33+lane] (consecutive: CF) ----
        #pragma unroll
        for (int c = 0; c < 32; c++) sm[lane * 33 + c] = v[c];
        __syncwarp();
        #pragma unroll
        for (int j = 0; j < 32; j++) v[j] = sm[j * 33 + lane];

        // ---- FWHT32 over new register index (element bits 2..6) ----
        #pragma unroll
        for (int m = 1; m < 32; m <<= 1) {
            #pragma unroll
            for (int p = 0; p < 32; p++) {
                if ((p & m) == 0) {
                    float u = v[p], w = v[p | m];
                    v[p]     = u + w;
                    v[p | m] = u - w;
                }
            }
        }

        // ---- transpose back (each thread overwrites exactly the words it
        //      just read -> no sync needed before the writes) ----
        #pragma unroll
        for (int j = 0; j < 32; j++) sm[j * 33 + lane] = v[j];
        __syncwarp();
        #pragma unroll
        for (int c = 0; c < 32; c++) v[c] = sm[lane * 33 + c];

        // ---- epilogue: scale/shift (L1-resident), streaming store ----
        {
            float4* __restrict__ po = xo4 + (size_t)row * 256u;
            #pragma unroll
            for (int k = 0; k < 8; k++) {
                float4 s4 = __ldg(&sc4[k * 32 + lane]);
                float4 h4 = __ldg(&sh4[k * 32 + lane]);
                float4 r;
                r.x = fmaf(s4.x * inv, v[4*k+0], h4.x);
                r.y = fmaf(s4.y * inv, v[4*k+1], h4.y);
                r.z = fmaf(s4.z * inv, v[4*k+2], h4.z);
                r.w = fmaf(s4.w * inv, v[4*k+3], h4.w);
                __stcs(&po[k * 32 + lane], r);
            }
        }

        // ---- rotate pipeline ----
        #pragma unroll
        for (int k = 0; k < 8; k++) t[k] = tn[k];
        row = next;
        // next-iter transpose writes touch only words this thread last read: safe
    }
}

extern "C" void kernel_launch(void* const* d_in, const int* in_sizes, int n_in,
                              void* d_out, int out_size)
{
    const float* x     = (const float*)d_in[0];
    const float* scale = (const float*)d_in[1];
    const float* shift = (const float*)d_in[2];
    float* out = (float*)d_out;

    const int nrows = in_sizes[0] / 1024;

    int sms = 148;
    cudaDeviceGetAttribute(&sms, cudaDevAttrMultiProcessorCount, 0);
    const int blocks = sms * 2;                 // 2 CTAs/SM, 16 warps/SM
    const int warp_stride = blocks * NWARPS;    // persistent grid-stride

    fwht1024_kernel<<<blocks, 32 * NWARPS>>>(x, scale, shift, out,
                                             nrows, warp_stride);
}

// round 8
// speedup vs baseline: 1.0061x; 1.0061x over previous
#include <cuda_runtime.h>
#include <cstddef>
#include <cstdint>

// One warp per row of 1024 floats, persistent grid-stride, with REGISTER-FREE
// software pipelining: the next row is prefetched into SMEM via cp.async.cg
// (LDGSTS: gmem->smem, no register buffer) while the current row is computed.
// This keeps 4KB per warp in flight ~continuously (24 warps/SM -> 96KB/SM,
// far above the ~18KB needed to cover DRAM latency at 8TB/s), fixing the MLP
// starvation that pinned R5-R7 at 70-74% DRAM.
//
// Per-warp SMEM: two 1056-float (4224B) buffers. Each buffer serves
// sequentially as (a) cp.async landing zone for a row (float4 slot k*33+lane
// holds global float4 32k+lane -- conflict-free LDS.128 read) and then
// (b) the stride-33 padded 32x32 transpose scratch for the same row.
//
// Math: thread owns 32 elements i = 128k+4lane+b as v[c], c=4k+b.
// FWHT1024 = FWHT32 over c-bits (i bits 0,1,7,8,9)
//          o FWHT32 over lane-bits (i bits 2..6) via padded-SMEM transpose.

#define NWARPS 8
#define BUF_FLOATS 1056            // 32*33 floats = 4224 B
#define SMEM_BYTES (NWARPS * 2 * BUF_FLOATS * 4)   // 67584 B per CTA

__device__ __forceinline__ void cp_async16(float* smem_dst, const float4* gmem_src)
{
    uint32_t s = (uint32_t)__cvta_generic_to_shared(smem_dst);
    asm volatile("cp.async.cg.shared.global [%0], [%1], 16;\n"
                 :: "r"(s), "l"(gmem_src));
}

__device__ __forceinline__ void fwht32(float* v)
{
    #pragma unroll
    for (int m = 1; m < 32; m <<= 1) {
        #pragma unroll
        for (int p = 0; p < 32; p++) {
            if ((p & m) == 0) {
                float u = v[p], w = v[p | m];
                v[p]     = u + w;
                v[p | m] = u - w;
            }
        }
    }
}

__global__ void __launch_bounds__(256, 3)
fwht1024_kernel(const float* __restrict__ x,
                const float* __restrict__ scale,
                const float* __restrict__ shift,
                float* __restrict__ out,
                int nrows, int warp_stride)
{
    extern __shared__ float smem[];
    const int wlocal = threadIdx.x >> 5;
    const int lane   = threadIdx.x & 31;
    float* __restrict__ buf0 = smem + wlocal * (2 * BUF_FLOATS);
    float* __restrict__ buf1 = buf0 + BUF_FLOATS;

    const float4* __restrict__ xin4 = reinterpret_cast<const float4*>(x);
    float4* __restrict__ xo4        = reinterpret_cast<float4*>(out);
    const float4* __restrict__ sc4  = reinterpret_cast<const float4*>(scale);
    const float4* __restrict__ sh4  = reinterpret_cast<const float4*>(shift);
    const float inv = 0.03125f;     // 1/sqrt(1024)

    int row = blockIdx.x * NWARPS + wlocal;

    // ---- prologue: prefetch first row into buf0 ----
    if (row < nrows) {
        const float4* g = xin4 + (size_t)row * 256u;
        #pragma unroll
        for (int k = 0; k < 8; k++)
            cp_async16(buf0 + (k * 33 + lane) * 4, &g[k * 32 + lane]);
    }
    asm volatile("cp.async.commit_group;\n" ::: "memory");

    int parity = 0;
    while (row < nrows) {
        const int next = row + warp_stride;
        float* __restrict__ cur = parity ? buf1 : buf0;
        float* __restrict__ nxt = parity ? buf0 : buf1;

        // guard: nxt's previous role (scratch of row-2*stride) fully read
        __syncwarp();

        // ---- prefetch next row (register-free, overlaps all compute) ----
        if (next < nrows) {
            const float4* g = xin4 + (size_t)next * 256u;
            #pragma unroll
            for (int k = 0; k < 8; k++)
                cp_async16(nxt + (k * 33 + lane) * 4, &g[k * 32 + lane]);
        }
        asm volatile("cp.async.commit_group;\n" ::: "memory");
        // allow 1 group outstanding (the one just issued) => current row done
        asm volatile("cp.async.wait_group 1;\n" ::: "memory");

        // ---- read current row from SMEM (each lane reads its own chunks) ----
        float v[32];
        const float4* __restrict__ cur4 = reinterpret_cast<const float4*>(cur);
        #pragma unroll
        for (int k = 0; k < 8; k++) {
            float4 t = cur4[k * 33 + lane];
            v[4*k+0] = t.x; v[4*k+1] = t.y; v[4*k+2] = t.z; v[4*k+3] = t.w;
        }
        __syncwarp();   // all lanes finished reading before scratch overwrites

        // ---- FWHT32 over register index (element bits 0,1,7,8,9) ----
        fwht32(v);

        // ---- transpose: write rows, read columns (stride-33: CF both ways) --
        #pragma unroll
        for (int c = 0; c < 32; c++) cur[lane * 33 + c] = v[c];
        __syncwarp();
        #pragma unroll
        for (int j = 0; j < 32; j++) v[j] = cur[j * 33 + lane];

        // ---- FWHT32 over new register index (element bits 2..6) ----
        fwht32(v);

        // ---- transpose back (overwrites exactly the words just read) ----
        #pragma unroll
        for (int j = 0; j < 32; j++) cur[j * 33 + lane] = v[j];
        __syncwarp();
        #pragma unroll
        for (int c = 0; c < 32; c++) v[c] = cur[lane * 33 + c];

        // ---- epilogue: scale/shift (L1-resident), streaming store ----
        {
            float4* __restrict__ po = xo4 + (size_t)row * 256u;
            #pragma unroll
            for (int k = 0; k < 8; k++) {
                float4 s4 = __ldg(&sc4[k * 32 + lane]);
                float4 h4 = __ldg(&sh4[k * 32 + lane]);
                float4 r;
                r.x = fmaf(s4.x * inv, v[4*k+0], h4.x);
                r.y = fmaf(s4.y * inv, v[4*k+1], h4.y);
                r.z = fmaf(s4.z * inv, v[4*k+2], h4.z);
                r.w = fmaf(s4.w * inv, v[4*k+3], h4.w);
                __stcs(&po[k * 32 + lane], r);
            }
        }

        row = next;
        parity ^= 1;
    }
}

extern "C" void kernel_launch(void* const* d_in, const int* in_sizes, int n_in,
                              void* d_out, int out_size)
{
    const float* x     = (const float*)d_in[0];
    const float* scale = (const float*)d_in[1];
    const float* shift = (const float*)d_in[2];
    float* out = (float*)d_out;

    const int nrows = in_sizes[0] / 1024;

    int sms = 148;
    cudaDeviceGetAttribute(&sms, cudaDevAttrMultiProcessorCount, 0);

    cudaFuncSetAttribute(fwht1024_kernel,
                         cudaFuncAttributeMaxDynamicSharedMemorySize,
                         SMEM_BYTES);

    const int blocks = sms * 3;                 // 3 CTAs/SM, 24 warps/SM
    const int warp_stride = blocks * NWARPS;    // persistent grid-stride

    fwht1024_kernel<<<blocks, 32 * NWARPS, SMEM_BYTES>>>(x, scale, shift, out,
                                                         nrows, warp_stride);
}